// round 6
// baseline (speedup 1.0000x reference)
#include <cuda_runtime.h>
#include <math.h>

#define BB 8
#define VV 2048
#define DD 16
#define FF 64
#define EMBD 32
#define HID 32
#define FEAT 16
#define BV (BB*VV)            // 16384
#define BVD (BV*DD)           // 262144
#define VD (VV*DD)            // 32768
#define NC (BV+1)             // 16385 classes (+1 global masked class)
#define NCPAD (65*256)        // 16640
#define BIGC 1e9f

typedef unsigned long long ull;

// ---------------- packed f32x2 helpers ----------------------------------------
__device__ __forceinline__ ull pack2(float lo, float hi){
    ull r;
    asm("mov.b64 %0, {%1, %2};" : "=l"(r) : "f"(lo), "f"(hi));
    return r;
}
__device__ __forceinline__ void unpack2(ull v, float& lo, float& hi){
    asm("mov.b64 {%0, %1}, %2;" : "=f"(lo), "=f"(hi) : "l"(v));
}
__device__ __forceinline__ void fma2(ull& d, ull a, ull b){
    asm("fma.rn.f32x2 %0, %1, %2, %0;" : "+l"(d) : "l"(a), "l"(b));
}
// padded smem column offset: insert 4-float pad every 32 cols (bank decorrelation)
__device__ __forceinline__ int padoff(int col){ return col + ((col>>5)<<2); }

// ---------------- scratch (device globals) -----------------------------------
__device__ float g_enc[BV*FF];
__device__ float g_S[NCPAD*FF];      // per-class state
__device__ float g_H[NCPAD*FF];      // per-class tanh(state@W+b)
__device__ float g_sc[NCPAD];        // per-class gat score
__device__ float g_agg[BV*FF];       // per-node agg
__device__ float g_nwc[NCPAD];       // per-class decoder output
__device__ float g_attnin[BVD];
__device__ float g_norm[BVD];
__device__ float g_dualvars[BV];
__device__ float g_fc[BB];
__device__ float g_dq[BVD/256];

// ---------------- 1. fused emb-normalize + encoder + S init -------------------
__global__ void k_enc(const float* __restrict__ nf, const float* __restrict__ emb,
                      const float* __restrict__ W, const float* __restrict__ bvec){
    if (blockIdx.x >= BV/4){
        int i = (blockIdx.x - BV/4)*256 + threadIdx.x;     // float4 units, 4096 total
        ((float4*)(g_S + (size_t)BV*FF))[i] = make_float4(0.f,0.f,0.f,0.f);
        return;
    }
    __shared__ float sEmb[4*EMBD];
    int t = threadIdx.x;
    int w = t >> 5, lane = t & 31;
    if (w < 4){
        int v = (blockIdx.x*4 + w) & (VV-1);
        float x = emb[v*EMBD + lane];
        float s = x*x;
        #pragma unroll
        for (int o=16;o;o>>=1) s += __shfl_xor_sync(0xffffffffu, s, o);
        float nrm = sqrtf(s);
        float scale = fminf(1.0f, 1.0f / fmaxf(nrm, 1e-12f));
        sEmb[w*EMBD + lane] = x*scale;
    }
    __syncthreads();
    int nl = t >> 6, f = t & 63;
    int node = blockIdx.x*4 + nl;
    float acc = bvec[f];
    const float* ev = sEmb + nl*EMBD;
    const float* nr = nf + node*FEAT;
    #pragma unroll
    for (int k=0;k<EMBD;k++) acc += ev[k]*W[k*FF+f];
    #pragma unroll
    for (int k=0;k<FEAT;k++) acc += nr[k]*W[(EMBD+k)*FF+f];
    g_enc[node*FF+f] = acc;
    g_S[(size_t)node*FF+f] = acc;
}

// ---------------- 2. per-class GAT: H = tanh(S@W+b), sc = H.a ------------------
// 128 rows/block, 512 threads. thread = 2 rows x 8 cols. Padded weight layout.
#define GSTRIDE 72
#define GAT_SMEM ((64*GSTRIDE)*4 + (64*64)*8)
__global__ void __launch_bounds__(512) k_gat(const float* __restrict__ W,
                                             const float* __restrict__ bvec,
                                             const float* __restrict__ gat_a){
    extern __shared__ float sh[];
    float*  Ws  = sh;                              // [64][GSTRIDE]
    float2* ss2 = (float2*)(sh + 64*GSTRIDE);      // [64 rp][64 k]
    int t = threadIdx.x;
    size_t base = (size_t)blockIdx.x * 128;
    for (int i=t;i<64*64;i+=512){
        int k = i>>6, col = i&63;
        Ws[k*GSTRIDE + padoff(col)] = W[i];
    }
    for (int i=t;i<64*64;i+=512){
        int rp = i>>6, k = i&63;
        size_t g0 = (base + rp*2)*FF + k;
        int sw = rp*64 + (k ^ ((rp<<1)&31));
        ss2[sw] = make_float2(g_S[g0], g_S[g0 + FF]);
    }
    __syncthreads();
    int cg = t & 7, rp = t >> 3;
    int csw = (rp<<1)&31;
    const float2* ssp = ss2 + rp*64;
    int f = cg*8;
    int og = padoff(f);
    ull a0[4], a1[4];
    {
        float b8[8];
        *(float4*)&b8[0] = __ldg((const float4*)(bvec+f));
        *(float4*)&b8[4] = __ldg((const float4*)(bvec+f+4));
        #pragma unroll
        for (int j=0;j<4;j++){ a0[j] = pack2(b8[2*j], b8[2*j+1]); a1[j] = a0[j]; }
    }
    #pragma unroll 4
    for (int k=0;k<64;k++){
        float2 sp = ssp[k ^ csw];
        ull s0 = pack2(sp.x, sp.x);
        ull s1 = pack2(sp.y, sp.y);
        const float* wb = Ws + k*GSTRIDE + og;
        ulonglong2 w0 = *(const ulonglong2*)(wb);
        ulonglong2 w1 = *(const ulonglong2*)(wb+4);
        fma2(a0[0], w0.x, s0); fma2(a0[1], w0.y, s0);
        fma2(a0[2], w1.x, s0); fma2(a0[3], w1.y, s0);
        fma2(a1[0], w0.x, s1); fma2(a1[1], w0.y, s1);
        fma2(a1[2], w1.x, s1); fma2(a1[3], w1.y, s1);
    }
    float av[8];
    *(float4*)&av[0] = __ldg((const float4*)(gat_a+f));
    *(float4*)&av[4] = __ldg((const float4*)(gat_a+f+4));
    float hv0[8], hv1[8];
    float sc0 = 0.f, sc1 = 0.f;
    #pragma unroll
    for (int j=0;j<4;j++){
        float xa,xb;
        unpack2(a0[j], xa, xb);
        hv0[2*j] = tanhf(xa); hv0[2*j+1] = tanhf(xb);
        sc0 += hv0[2*j]*av[2*j] + hv0[2*j+1]*av[2*j+1];
        unpack2(a1[j], xa, xb);
        hv1[2*j] = tanhf(xa); hv1[2*j+1] = tanhf(xb);
        sc1 += hv1[2*j]*av[2*j] + hv1[2*j+1]*av[2*j+1];
    }
    size_t r0 = base + rp*2;
    *(float4*)(g_H + r0*FF + f)          = *(float4*)&hv0[0];
    *(float4*)(g_H + r0*FF + f + 4)      = *(float4*)&hv0[4];
    *(float4*)(g_H + (r0+1)*FF + f)      = *(float4*)&hv1[0];
    *(float4*)(g_H + (r0+1)*FF + f + 4)  = *(float4*)&hv1[4];
    #pragma unroll
    for (int o=1;o<8;o<<=1){
        sc0 += __shfl_xor_sync(0xffffffffu, sc0, o);
        sc1 += __shfl_xor_sync(0xffffffffu, sc1, o);
    }
    if (cg == 0){ g_sc[r0] = sc0; g_sc[r0+1] = sc1; }
}

// ---------------- 3. per-node softmax(D) + agg from class rows ------------------
__global__ void k_attnagg(const int* __restrict__ adj, const int* __restrict__ num_nodes){
    int lane = threadIdx.x & 31;
    int node = blockIdx.x*8 + (threadIdx.x >> 5);
    int b = node >> 11;
    int nn = num_nodes[b];
    int c = 0;
    float sc = -1e30f;
    if (lane < DD){
        int a = adj[node*DD+lane];
        bool m = (a==nn);
        c = m ? BV : ((b<<11)+a);
        sc = g_sc[c] - (m ? BIGC : 0.f);
    }
    float mx = sc;
    #pragma unroll
    for (int o=16;o;o>>=1) mx = fmaxf(mx, __shfl_xor_sync(0xffffffffu, mx, o));
    float e = (lane < DD) ? __expf(sc - mx) : 0.f;
    float sm = e;
    #pragma unroll
    for (int o=16;o;o>>=1) sm += __shfl_xor_sync(0xffffffffu, sm, o);
    float attn = e / sm;
    float a0=0.f, a1=0.f;
    #pragma unroll
    for (int d=0;d<DD;d++){
        float ad = __shfl_sync(0xffffffffu, attn, d);
        int  cd = __shfl_sync(0xffffffffu, c, d);
        const float* hr = g_H + (size_t)cd*FF;
        a0 += ad * hr[lane];
        a1 += ad * hr[lane + 32];
    }
    g_agg[node*FF + lane]      = a0;
    g_agg[node*FF + lane + 32] = a1;
}

// ---------------- 4. per-class GRU: S = GRU(agg+enc, S) -------------------------
// 64 rows/block, 256 threads. thread = 2 rows x 8 cols x 6 gates. Padded weights.
#define WSTRIDE 216
#define GRU_SMEM ((2*64*WSTRIDE)*4 + 2*(32*64)*8)
__global__ void __launch_bounds__(256, 1) k_gru(const float* __restrict__ Wx,
                                                const float* __restrict__ Wh,
                                                const float* __restrict__ bvec){
    extern __shared__ float sh[];
    float*  Wxs = sh;                              // [64][WSTRIDE]
    float*  Whs = sh + 64*WSTRIDE;
    float2* ms2 = (float2*)(sh + 2*64*WSTRIDE);    // [32 rp][64 k]
    float2* ss2 = ms2 + 32*64;
    int t = threadIdx.x;
    size_t base = (size_t)blockIdx.x * 64;
    for (int k=0;k<64;k++){
        if (t < 192){
            int o = k*WSTRIDE + padoff(t);
            Wxs[o] = Wx[k*192 + t];
            Whs[o] = Wh[k*192 + t];
        }
    }
    for (int i=t;i<32*64;i+=256){
        int rp = i>>6, k = i&63;
        size_t gr0 = base + rp*2;
        size_t gr1 = gr0 + 1;
        int sw = rp*64 + (k ^ ((rp<<1)&31));
        float m0 = (gr0 < BV) ? (g_agg[gr0*FF+k] + g_enc[gr0*FF+k]) : 0.f;
        float m1 = (gr1 < BV) ? (g_agg[gr1*FF+k] + g_enc[gr1*FF+k]) : 0.f;
        ms2[sw] = make_float2(m0, m1);
        ss2[sw] = make_float2(g_S[gr0*FF + k], g_S[gr1*FF + k]);
    }
    __syncthreads();
    int cg = t & 7, rp = t >> 3;
    int csw = (rp<<1)&31;
    const float2* msp = ms2 + rp*64;
    const float2* ssp = ss2 + rp*64;
    int f = cg*8;
    int o0 = padoff(f), o1 = padoff(64+f), o2 = padoff(128+f);
    // acc: ax[r][0..3]=x0, [4..7]=x1, [8..11]=x2; ah likewise for h-gates
    ull ax[2][12], ah[2][12];
    #pragma unroll
    for (int r=0;r<2;r++)
        #pragma unroll
        for (int j=0;j<12;j++){ ax[r][j]=0ull; ah[r][j]=0ull; }
    #pragma unroll 4
    for (int k=0;k<64;k++){
        float2 mp = msp[k ^ csw];
        float2 sp = ssp[k ^ csw];
        ull m2[2] = { pack2(mp.x,mp.x), pack2(mp.y,mp.y) };
        ull s2[2] = { pack2(sp.x,sp.x), pack2(sp.y,sp.y) };
        const float* wb = Wxs + k*WSTRIDE;
        const float* vb = Whs + k*WSTRIDE;
        ulonglong2 w0 = *(const ulonglong2*)(wb+o0);
        ulonglong2 w1 = *(const ulonglong2*)(wb+o0+4);
        ulonglong2 w2 = *(const ulonglong2*)(wb+o1);
        ulonglong2 w3 = *(const ulonglong2*)(wb+o1+4);
        ulonglong2 w4 = *(const ulonglong2*)(wb+o2);
        ulonglong2 w5 = *(const ulonglong2*)(wb+o2+4);
        ulonglong2 v0 = *(const ulonglong2*)(vb+o0);
        ulonglong2 v1 = *(const ulonglong2*)(vb+o0+4);
        ulonglong2 v2 = *(const ulonglong2*)(vb+o1);
        ulonglong2 v3 = *(const ulonglong2*)(vb+o1+4);
        ulonglong2 v4 = *(const ulonglong2*)(vb+o2);
        ulonglong2 v5 = *(const ulonglong2*)(vb+o2+4);
        #pragma unroll
        for (int r=0;r<2;r++){
            fma2(ax[r][0],  w0.x, m2[r]); fma2(ax[r][1],  w0.y, m2[r]);
            fma2(ax[r][2],  w1.x, m2[r]); fma2(ax[r][3],  w1.y, m2[r]);
            fma2(ax[r][4],  w2.x, m2[r]); fma2(ax[r][5],  w2.y, m2[r]);
            fma2(ax[r][6],  w3.x, m2[r]); fma2(ax[r][7],  w3.y, m2[r]);
            fma2(ax[r][8],  w4.x, m2[r]); fma2(ax[r][9],  w4.y, m2[r]);
            fma2(ax[r][10], w5.x, m2[r]); fma2(ax[r][11], w5.y, m2[r]);
            fma2(ah[r][0],  v0.x, s2[r]); fma2(ah[r][1],  v0.y, s2[r]);
            fma2(ah[r][2],  v1.x, s2[r]); fma2(ah[r][3],  v1.y, s2[r]);
            fma2(ah[r][4],  v2.x, s2[r]); fma2(ah[r][5],  v2.y, s2[r]);
            fma2(ah[r][6],  v3.x, s2[r]); fma2(ah[r][7],  v3.y, s2[r]);
            fma2(ah[r][8],  v4.x, s2[r]); fma2(ah[r][9],  v4.y, s2[r]);
            fma2(ah[r][10], v5.x, s2[r]); fma2(ah[r][11], v5.y, s2[r]);
        }
    }
    float bz[8], br8[8], bh[8];
    *(float4*)&bz[0]  = __ldg((const float4*)(bvec+f));
    *(float4*)&bz[4]  = __ldg((const float4*)(bvec+f+4));
    *(float4*)&br8[0] = __ldg((const float4*)(bvec+64+f));
    *(float4*)&br8[4] = __ldg((const float4*)(bvec+64+f+4));
    *(float4*)&bh[0]  = __ldg((const float4*)(bvec+128+f));
    *(float4*)&bh[4]  = __ldg((const float4*)(bvec+128+f+4));
    #pragma unroll
    for (int r=0;r<2;r++){
        float o[8];
        #pragma unroll
        for (int j=0;j<4;j++){
            float x0a,x0b,x1a,x1b,x2a,x2b,h0a,h0b,h1a,h1b,h2a,h2b;
            unpack2(ax[r][j],   x0a,x0b);
            unpack2(ax[r][4+j], x1a,x1b);
            unpack2(ax[r][8+j], x2a,x2b);
            unpack2(ah[r][j],   h0a,h0b);
            unpack2(ah[r][4+j], h1a,h1b);
            unpack2(ah[r][8+j], h2a,h2b);
            float2 sold0 = ssp[(f+2*j)   ^ csw];
            float2 sold1 = ssp[(f+2*j+1) ^ csw];
            float sa = r ? sold0.y : sold0.x;
            float sb = r ? sold1.y : sold1.x;
            {
                float z    = 1.f/(1.f + __expf(-(x0a + bz[2*j]  + h0a)));
                float rr   = 1.f/(1.f + __expf(-(x1a + br8[2*j] + h1a)));
                float cand = tanhf(x2a + bh[2*j] + rr*h2a);
                o[2*j] = z*sa + (1.f - z)*cand;
            }
            {
                float z    = 1.f/(1.f + __expf(-(x0b + bz[2*j+1]  + h0b)));
                float rr   = 1.f/(1.f + __expf(-(x1b + br8[2*j+1] + h1b)));
                float cand = tanhf(x2b + bh[2*j+1] + rr*h2b);
                o[2*j+1] = z*sb + (1.f - z)*cand;
            }
        }
        size_t orow = (base + rp*2 + r) * FF;
        *(float4*)(g_S + orow + f)     = *(float4*)&o[0];
        *(float4*)(g_S + orow + f + 4) = *(float4*)&o[4];
    }
}

// ---------------- 5. 64->32->1 MLP head (decoder, per-class) ----------------------
__global__ void k_mlp(const float* __restrict__ W1, const float* __restrict__ b1,
                      const float* __restrict__ W2, const float* __restrict__ b2){
    __shared__ float S[128*65];
    __shared__ float W1s[64*32];
    __shared__ float b1s[32], W2s[32];
    int t = threadIdx.x;
    int base = blockIdx.x*128;
    for (int i=t;i<2048;i+=128) W1s[i] = W1[i];
    if (t < 32){ b1s[t] = b1[t]; W2s[t] = W2[t]; }
    for (int c=0;c<64;c++){
        int lin = c*128 + t;
        int r = lin >> 6, k = lin & 63;
        S[r*65 + k] = g_S[(size_t)base*FF + lin];
    }
    __syncthreads();
    if (base + t >= NC) return;
    float acc[32];
    #pragma unroll
    for (int h=0;h<32;h++) acc[h] = b1s[h];
    const float* myrow = S + t*65;
    for (int k=0;k<64;k++){
        float s = myrow[k];
        #pragma unroll
        for (int h=0;h<32;h++) acc[h] += s*W1s[k*32+h];
    }
    float o = b2[0];
    #pragma unroll
    for (int h=0;h<32;h++) o += tanhf(acc[h])*W2s[h];
    g_nwc[base + t] = o;
}

// ---------------- 6. incoming-gather softmax (expand fused) -----------------------
__global__ void k_inattn(const int* __restrict__ in_idx, const int* __restrict__ inv_adj,
                         const int* __restrict__ adj, const int* __restrict__ num_nodes){
    int lane = threadIdx.x & 31;
    int node = blockIdx.x*8 + (threadIdx.x >> 5);
    int b = node >> 11;
    int nn = num_nodes[b];
    float sc = -1e30f;
    if (lane < DD){
        int idx = in_idx[node*DD + lane];
        int a2 = adj[b*VD + idx];
        float inc = g_nwc[(a2==nn) ? BV : ((b<<11)+a2)];
        int ia = inv_adj[node*DD + lane];
        sc = inc - ((ia == nn) ? BIGC : 0.f);
    }
    float mx = sc;
    #pragma unroll
    for (int o=16;o;o>>=1) mx = fmaxf(mx, __shfl_xor_sync(0xffffffffu, mx, o));
    float e = (lane < DD) ? __expf(sc - mx) : 0.f;
    float sm = e;
    #pragma unroll
    for (int o=16;o;o>>=1) sm += __shfl_xor_sync(0xffffffffu, sm, o);
    if (lane < DD) g_attnin[node*DD + lane] = e / sm;
}

// ---------------- 7. rev-gather + masked softmax -> normalized ---------------------
__global__ void k_revnorm(const int* __restrict__ rev_idx, const int* __restrict__ adj,
                          const int* __restrict__ num_nodes){
    int lane = threadIdx.x & 31;
    int node = blockIdx.x*8 + (threadIdx.x >> 5);
    int b = node >> 11;
    float sc = -1e30f;
    if (lane < DD){
        int ridx = rev_idx[node*DD + lane];
        float val = g_attnin[b*VD + ridx];
        int a = adj[node*DD + lane];
        sc = val - ((a == num_nodes[b]) ? BIGC : 0.f);
    }
    float mx = sc;
    #pragma unroll
    for (int o=16;o;o>>=1) mx = fmaxf(mx, __shfl_xor_sync(0xffffffffu, mx, o));
    float e = (lane < DD) ? __expf(sc - mx) : 0.f;
    float sm = e;
    #pragma unroll
    for (int o=16;o;o>>=1) sm += __shfl_xor_sync(0xffffffffu, sm, o);
    if (lane < DD) g_norm[node*DD + lane] = e / sm;
}

// ---------------- 8. flow fixed-point on node vector t, 1 block/batch ---------------
#define FLOW_SMEM ((VD + VV + VV + 1024) * (int)sizeof(float))
__global__ void __launch_bounds__(1024) k_flow(const float* __restrict__ demands,
                                               const int* __restrict__ inv_adj,
                                               const int* __restrict__ in_idx,
                                               const int* __restrict__ num_nodes){
    extern __shared__ float sh[];
    float* wT  = sh;              // [DD][VV] transposed weights
    float* ts  = sh + VD;         // VV
    float* sup = ts + VV;         // VV
    float* red = sup + VV;        // 1024
    int b = blockIdx.x, t = threadIdx.x;
    int nn = num_nodes[b];
    unsigned int sp[2][8];        // packed source node indices (16-bit)
    float nsq[2];
    #pragma unroll
    for (int n=0;n<2;n++){
        int v = t + n*1024;
        size_t ebase = ((size_t)b*VV + v)*DD;
        int ia[DD], m[DD];
        #pragma unroll
        for (int d=0;d<DD;d+=4){
            *(int4*)&ia[d] = __ldg((const int4*)(inv_adj + ebase + d));
            *(int4*)&m[d]  = __ldg((const int4*)(in_idx  + ebase + d));
        }
        float nrm[DD];
        #pragma unroll
        for (int d=0;d<DD;d+=4)
            *(float4*)&nrm[d] = __ldg((const float4*)(g_norm + (size_t)b*VD + v*DD + d));
        float q = 0.f;
        #pragma unroll
        for (int d=0;d<DD;d++) q += nrm[d]*nrm[d];
        nsq[n] = q;
        #pragma unroll
        for (int d=0;d<DD;d++){
            float wv = (ia[d]==nn) ? 0.f : g_norm[(size_t)b*VD + m[d]];
            wT[d*VV + v] = wv;
            int sv = m[d] >> 4;
            if ((d&1)==0) sp[n][d>>1] = (unsigned int)sv;
            else          sp[n][d>>1] |= ((unsigned int)sv) << 16;
        }
        float s = fmaxf(-demands[b*VV + v], 0.f);
        sup[v] = s;
        ts[v] = s;
    }
    __syncthreads();
    for (int it=0; it<10; it++){
        float acc[2] = {0.f, 0.f};
        #pragma unroll
        for (int n=0;n<2;n++){
            int v = t + n*1024;
            #pragma unroll
            for (int d=0;d<DD;d++){
                unsigned int pk = sp[n][d>>1];
                int sv = (d&1) ? (pk>>16) : (pk & 0xffff);
                acc[n] += wT[d*VV + v] * ts[sv];
            }
        }
        __syncthreads();
        ts[t]        = sup[t]        + acc[0];
        ts[t + 1024] = sup[t + 1024] + acc[1];
        __syncthreads();
    }
    float c = nsq[0]*ts[t]*ts[t] + nsq[1]*ts[t+1024]*ts[t+1024];
    red[t] = c; __syncthreads();
    for (int s=512; s>0; s>>=1){ if (t < s) red[t] += red[t+s]; __syncthreads(); }
    if (t == 0) g_fc[b] = red[0];
}

// ---------------- 9. fused node-state sum + dual MLP --------------------------------
__global__ void k_dualhead(const int* __restrict__ adj, const int* __restrict__ num_nodes,
                           const float* __restrict__ W1, const float* __restrict__ b1,
                           const float* __restrict__ W2, const float* __restrict__ b2){
    __shared__ float S[128*65];
    __shared__ float W1s[64*32];
    __shared__ float b1s[32], W2s[32];
    int t = threadIdx.x;              // 128
    int base = blockIdx.x*128;
    for (int i=t;i<2048;i+=128) W1s[i] = W1[i];
    if (t < 32){ b1s[t] = b1[t]; W2s[t] = W2[t]; }
    int w = t >> 5, lane = t & 31;
    for (int li=0; li<32; li++){
        int l = w*32 + li;
        int node = base + l;
        int b = node >> 11;
        int nn = num_nodes[b];
        int c = 0;
        if (lane < DD){
            int a = adj[node*DD + lane];
            c = (a==nn) ? BV : ((b<<11)+a);
        }
        float s0=0.f, s1=0.f;
        #pragma unroll
        for (int d=0;d<DD;d++){
            int cd = __shfl_sync(0xffffffffu, c, d);
            const float* sr = g_S + (size_t)cd*FF;
            s0 += sr[lane];
            s1 += sr[lane + 32];
        }
        S[l*65 + lane]      = s0;
        S[l*65 + 32 + lane] = s1;
    }
    __syncthreads();
    float acc[32];
    #pragma unroll
    for (int h=0;h<32;h++) acc[h] = b1s[h];
    const float* myrow = S + t*65;
    for (int k=0;k<64;k++){
        float s = myrow[k];
        #pragma unroll
        for (int h=0;h<32;h++) acc[h] += s*W1s[k*32+h];
    }
    float o = b2[0];
    #pragma unroll
    for (int h=0;h<32;h++) o += tanhf(acc[h])*W2s[h];
    g_dualvars[base + t] = o;
}

// ---------------- 10. dual iterations + quad cost + demand fold ----------------------
__global__ void k_dual(const int* __restrict__ adj, const int* __restrict__ num_nodes,
                       const float* __restrict__ demands){
    __shared__ float red[256];
    int idx = blockIdx.x*256 + threadIdx.x;
    int b = idx >> 15; int node = idx >> 4;
    int a = adj[idx]; int nn = num_nodes[b];
    float mask = (a==nn) ? 1.f : 0.f;
    float valid = 1.f - mask;
    float dv  = g_dualvars[node];
    float dtr = g_dualvars[(b<<11) + a] * valid;
    float dd  = dtr - mask*dv;
    float f = 0.f, ac = 0.f;
    #pragma unroll
    for (int i=0;i<10;i++){
        float g = 2.f*f + dd;
        ac = 0.9f*ac + 0.01f*g;
        f = fmaxf(f - ac, 0.f) * valid;
    }
    float c = f*f + dd*f;
    if ((idx & 15) == 0) c -= dv * demands[node];     // fold dual_demand (once per node)
    red[threadIdx.x] = c; __syncthreads();
    for (int s=128; s>0; s>>=1){ if (threadIdx.x < s) red[threadIdx.x] += red[threadIdx.x+s]; __syncthreads(); }
    if (threadIdx.x == 0) g_dq[blockIdx.x] = red[0];
}

// ---------------- 11. finalize: out[b] = fc - sum(dq partials) ------------------------
__global__ void k_finalize(float* __restrict__ out){
    int w = threadIdx.x >> 5, lane = threadIdx.x & 31;
    if (w < BB){
        float dq = 0.f;
        #pragma unroll
        for (int i=0;i<4;i++) dq += g_dq[w*128 + lane + 32*i];
        #pragma unroll
        for (int o=16;o;o>>=1) dq += __shfl_xor_sync(0xffffffffu, dq, o);
        if (lane == 0) out[w] = g_fc[w] - dq;
    }
}

// ---------------- launcher -------------------------------------------------------------
extern "C" void kernel_launch(void* const* d_in, const int* in_sizes, int n_in,
                              void* d_out, int out_size){
    const float* node_features = (const float*)d_in[0];
    const float* demands       = (const float*)d_in[1];
    const float* emb           = (const float*)d_in[2];
    const float* enc_W         = (const float*)d_in[3];
    const float* enc_b         = (const float*)d_in[4];
    const float* gat_W         = (const float*)d_in[5];
    const float* gat_b         = (const float*)d_in[6];
    const float* gat_a         = (const float*)d_in[7];
    const float* gru_Wx        = (const float*)d_in[8];
    const float* gru_Wh        = (const float*)d_in[9];
    const float* gru_b         = (const float*)d_in[10];
    const float* dec_W1        = (const float*)d_in[11];
    const float* dec_b1        = (const float*)d_in[12];
    const float* dec_W2        = (const float*)d_in[13];
    const float* dec_b2        = (const float*)d_in[14];
    const float* dual_W1       = (const float*)d_in[15];
    const float* dual_b1       = (const float*)d_in[16];
    const float* dual_W2       = (const float*)d_in[17];
    const float* dual_b2       = (const float*)d_in[18];
    const int*   adj           = (const int*)d_in[19];
    const int*   inv_adj       = (const int*)d_in[20];
    const int*   in_idx        = (const int*)d_in[21];
    const int*   rev_idx       = (const int*)d_in[22];
    const int*   num_nodes     = (const int*)d_in[23];
    float* out = (float*)d_out;

    cudaFuncSetAttribute(k_gru,  cudaFuncAttributeMaxDynamicSharedMemorySize, GRU_SMEM);
    cudaFuncSetAttribute(k_gat,  cudaFuncAttributeMaxDynamicSharedMemorySize, GAT_SMEM);
    cudaFuncSetAttribute(k_flow, cudaFuncAttributeMaxDynamicSharedMemorySize, FLOW_SMEM);

    k_enc<<<BV/4 + 16, 256>>>(node_features, emb, enc_W, enc_b);

    for (int l=0; l<2; l++){
        k_gat    <<<NCPAD/128, 512, GAT_SMEM>>>(gat_W, gat_b, gat_a);
        k_attnagg<<<BV/8, 256>>>(adj, num_nodes);
        k_gru    <<<NCPAD/64, 256, GRU_SMEM>>>(gru_Wx, gru_Wh, gru_b);
    }

    // flow branch
    k_mlp<<<(NC+127)/128, 128>>>(dec_W1, dec_b1, dec_W2, dec_b2);
    k_inattn <<<BV/8, 256>>>(in_idx, inv_adj, adj, num_nodes);
    k_revnorm<<<BV/8, 256>>>(rev_idx, adj, num_nodes);
    k_flow<<<BB, 1024, FLOW_SMEM>>>(demands, inv_adj, in_idx, num_nodes);

    // dual branch
    k_dualhead<<<BV/128, 128>>>(adj, num_nodes, dual_W1, dual_b1, dual_W2, dual_b2);
    k_dual<<<BVD/256, 256>>>(adj, num_nodes, demands);

    k_finalize<<<1, 256>>>(out);
}